// round 14
// baseline (speedup 1.0000x reference)
#include <cuda_runtime.h>
#include <cuda_fp16.h>

// out[b, o] = max_i min(x[b, i], W[i, o])   (fuzzy max-min composition)
// x: [1024, 512] f32, W: [512, 512] f32, out: [1024, 512] f32.
//
// R14: candidate-parallel graduated scan, widened to 8 warps/block.
//   R13 (4 warps) was still latency-bound (issue 31%): chain of 4 dependent
//   load-rounds. Now 8 warps split candidate rows 8 ways -> 32 rows/iter ->
//   chain length 2 for E[C1]=64, and 4 blocks/SM -> 32 warps/SM (occ 50%).
//   Tier structure (G1: x>=0.875, G2: x>=0.75, dense fallback) unchanged --
//   sound for any input (fp16-exact thresholds, monotone rounding).

#define B_DIM   1024
#define IN_F    512
#define OUT_F   512
#define THREADS 256
#define NWARP   8
#define TH1     0.875f
#define TH2     0.75f

// scratch: w packed-half2 [k][n/2]  (512 KB, L2-resident)
__device__ __align__(16) unsigned g_wh[IN_F * OUT_F / 2];

// ---------------- prepass: w f32 -> packed half2 [k][n/2] ----------------
__global__ __launch_bounds__(256)
void prep_w(const float* __restrict__ w)
{
    const int t = threadIdx.x;
    const int f4base = blockIdx.x * 512 + t * 2;
    float4 a = ((const float4*)w)[f4base];
    float4 b = ((const float4*)w)[f4base + 1];
    __half2 h0 = __floats2half2_rn(a.x, a.y);
    __half2 h1 = __floats2half2_rn(a.z, a.w);
    __half2 h2 = __floats2half2_rn(b.x, b.y);
    __half2 h3 = __floats2half2_rn(b.z, b.w);
    ((uint4*)g_wh)[blockIdx.x * 256 + t] = make_uint4(
        *(unsigned*)&h0, *(unsigned*)&h1, *(unsigned*)&h2, *(unsigned*)&h3);
}

// ---------------- main ----------------
__global__ __launch_bounds__(THREADS, 4)
void maxmin_cp8(const float* __restrict__ x, float* __restrict__ out)
{
    __shared__ uint2    meta[IN_F + 32];     // {w row elem-offset, dup-half2 x}
    __shared__ unsigned xdup[IN_F];          // natural order (dense fallback)
    __shared__ unsigned mrg[NWARP][OUT_F/2]; // per-warp partial bests (8 KB)
    __shared__ int s_c1, s_c2;

    const int t    = threadIdx.x;
    const int b    = blockIdx.x;
    const int warp = t >> 5;
    const int lane = t & 31;
    const unsigned lmlt = (1u << lane) - 1u;

    if (t == 0) { s_c1 = 0; s_c2 = 0; }
    __syncthreads();

    // ---- classify 2 x values/thread + reserve compaction slots ----
    float2 xq = ((const float2*)x)[b * (IN_F / 2) + t];
    float xv[2] = {xq.x, xq.y};
    unsigned m1[2], m2[2];
    int      b1[2], b2[2];
    bool     p1[2], p2[2];
#pragma unroll
    for (int u = 0; u < 2; u++) {
        __half2 d = __float2half2_rn(xv[u]);
        xdup[t * 2 + u] = *(unsigned*)&d;
        p1[u] = (xv[u] >= TH1);
        p2[u] = (!p1[u]) && (xv[u] >= TH2);
        m1[u] = __ballot_sync(0xFFFFFFFFu, p1[u]);
        m2[u] = __ballot_sync(0xFFFFFFFFu, p2[u]);
        int base1 = 0, base2 = 0;
        if (lane == 0) {
            if (m1[u]) base1 = atomicAdd(&s_c1, __popc(m1[u]));
            if (m2[u]) base2 = atomicAdd(&s_c2, __popc(m2[u]));
        }
        b1[u] = __shfl_sync(0xFFFFFFFFu, base1, 0);
        b2[u] = __shfl_sync(0xFFFFFFFFu, base2, 0);
    }
    __syncthreads();
    const int C1 = s_c1;
    const int C2 = s_c2;

    // ---- scatter: G1 at [0,C1), G2 at [C1,C1+C2); zero-pad 32 ----
#pragma unroll
    for (int u = 0; u < 2; u++) {
        int idx = t * 2 + u;
        unsigned xd = xdup[idx];
        if (p1[u])
            meta[b1[u] + __popc(m1[u] & lmlt)] =
                make_uint2((unsigned)(idx * (OUT_F / 2)), xd);
        else if (p2[u])
            meta[C1 + b2[u] + __popc(m2[u] & lmlt)] =
                make_uint2((unsigned)(idx * (OUT_F / 2)), xd);
    }
    if (t < 32) meta[C1 + C2 + t] = make_uint2(0u, 0u);  // x=0 pad: harmless
    __syncthreads();

    // ---- candidate-parallel scan: iter covers 32 rows (8 warps x 4) ----
    // lane owns 16 outputs: uints co..co+7 of a packed W row (2x LDG.128).
    const int co = lane * 8;
    __half2 acc[8];
#pragma unroll
    for (int i = 0; i < 8; i++) acc[i] = __float2half2_rn(0.f);

    auto scan_rows = [&](int rbeg, int nit) {
#pragma unroll 1
        for (int it = 0; it < nit; it++) {
            const int rb = rbeg + it * 32 + warp * 4;
            uint4 v[8];
            unsigned xh[4];
#pragma unroll
            for (int q = 0; q < 4; q++) {          // 8 independent LDG.128
                uint2 m = meta[rb + q];
                xh[q] = m.y;
                const uint4* p = (const uint4*)&g_wh[m.x + co];
                v[2 * q]     = p[0];
                v[2 * q + 1] = p[1];
            }
#pragma unroll
            for (int q = 0; q < 4; q++) {
                __half2 xw = *(__half2*)&xh[q];
                acc[0] = __hmax2(acc[0], __hmin2(xw, *(__half2*)&v[2*q].x));
                acc[1] = __hmax2(acc[1], __hmin2(xw, *(__half2*)&v[2*q].y));
                acc[2] = __hmax2(acc[2], __hmin2(xw, *(__half2*)&v[2*q].z));
                acc[3] = __hmax2(acc[3], __hmin2(xw, *(__half2*)&v[2*q].w));
                acc[4] = __hmax2(acc[4], __hmin2(xw, *(__half2*)&v[2*q+1].x));
                acc[5] = __hmax2(acc[5], __hmin2(xw, *(__half2*)&v[2*q+1].y));
                acc[6] = __hmax2(acc[6], __hmin2(xw, *(__half2*)&v[2*q+1].z));
                acc[7] = __hmax2(acc[7], __hmin2(xw, *(__half2*)&v[2*q+1].w));
            }
        }
    };

    // merge 8 warps' partials; thread t ends up owning outputs 2t, 2t+1
    auto merge_read = [&](__half2& best) {
        *(uint4*)&mrg[warp][co] =
            make_uint4(*(unsigned*)&acc[0], *(unsigned*)&acc[1],
                       *(unsigned*)&acc[2], *(unsigned*)&acc[3]);
        *(uint4*)&mrg[warp][co + 4] =
            make_uint4(*(unsigned*)&acc[4], *(unsigned*)&acc[5],
                       *(unsigned*)&acc[6], *(unsigned*)&acc[7]);
        __syncthreads();
        unsigned r0 = mrg[0][t], r1 = mrg[1][t], r2 = mrg[2][t], r3 = mrg[3][t];
        unsigned r4 = mrg[4][t], r5 = mrg[5][t], r6 = mrg[6][t], r7 = mrg[7][t];
        __half2 h01 = __hmax2(*(__half2*)&r0, *(__half2*)&r1);
        __half2 h23 = __hmax2(*(__half2*)&r2, *(__half2*)&r3);
        __half2 h45 = __hmax2(*(__half2*)&r4, *(__half2*)&r5);
        __half2 h67 = __hmax2(*(__half2*)&r6, *(__half2*)&r7);
        best = __hmax2(__hmax2(h01, h23), __hmax2(h45, h67));
    };

    // ---- tier 1 ----
    const int nit1 = (C1 + 31) >> 5;
    scan_rows(0, nit1);
    __half2 best;
    merge_read(best);

    const __half2 T1h = __float2half2_rn(TH1);
    if (!__syncthreads_and(__hbge2(best, T1h))) {
        // ---- tier 2: remaining rows of G1+G2 ----
        const int done = nit1 * 32;
        const int rem  = C1 + C2 - done;
        if (rem > 0) scan_rows(done, (rem + 31) >> 5);
        merge_read(best);
        const __half2 T2h = __float2half2_rn(TH2);
        if (!__syncthreads_and(__hbge2(best, T2h))) {
            // ---- dense fallback (arbitrary inputs; ~never for uniform) ----
#pragma unroll 8
            for (int j = 0; j < IN_F; j++) {
                unsigned wv = g_wh[j * (OUT_F / 2) + t];
                unsigned xd = xdup[j];
                best = __hmax2(best, __hmin2(*(__half2*)&xd, *(__half2*)&wv));
            }
        }
    }

    // ---- store 2 outputs (float2, coalesced) ----
    float2 o = __half22float2(best);
    *(float2*)(out + b * OUT_F + t * 2) = o;
}

extern "C" void kernel_launch(void* const* d_in, const int* in_sizes, int n_in,
                              void* d_out, int out_size)
{
    const float* x = (const float*)d_in[0];   // [1024, 512]
    const float* w = (const float*)d_in[1];   // [512, 512]
    float* out = (float*)d_out;               // [1024, 512]

    prep_w<<<128, 256>>>(w);
    maxmin_cp8<<<B_DIM, THREADS>>>(x, out);
}

// round 15
// speedup vs baseline: 1.1552x; 1.1552x over previous
#include <cuda_runtime.h>
#include <cuda_fp16.h>

// out[b, o] = max_i min(x[b, i], W[i, o])   (fuzzy max-min composition)
// x: [1024, 512] f32, W: [512, 512] f32, out: [1024, 512] f32.
//
// R15: R13 (candidate-parallel graduated scan, 4 warps, 16-row granularity)
// with residency raised to 8 blocks/SM (launch_bounds(128,8); regs==64 cap).
// R13 was latency-bound (issue 31%, L1 48%): 4 dependent L2 rounds per block
// with only 24 warps/SM covering them. R14 showed wider blocks add over-scan;
// this keeps R13's byte count and just adds warps.

#define B_DIM   1024
#define IN_F    512
#define OUT_F   512
#define THREADS 128
#define TH1     0.875f
#define TH2     0.75f

// scratch: w packed-half2 [k][n/2]  (512 KB, L2-resident)
__device__ __align__(16) unsigned g_wh[IN_F * OUT_F / 2];

// ---------------- prepass: w f32 -> packed half2 [k][n/2] ----------------
__global__ __launch_bounds__(256)
void prep_w(const float* __restrict__ w)
{
    const int t = threadIdx.x;
    const int f4base = blockIdx.x * 512 + t * 2;
    float4 a = ((const float4*)w)[f4base];
    float4 b = ((const float4*)w)[f4base + 1];
    __half2 h0 = __floats2half2_rn(a.x, a.y);
    __half2 h1 = __floats2half2_rn(a.z, a.w);
    __half2 h2 = __floats2half2_rn(b.x, b.y);
    __half2 h3 = __floats2half2_rn(b.z, b.w);
    ((uint4*)g_wh)[blockIdx.x * 256 + t] = make_uint4(
        *(unsigned*)&h0, *(unsigned*)&h1, *(unsigned*)&h2, *(unsigned*)&h3);
}

// ---------------- main ----------------
__global__ __launch_bounds__(THREADS, 8)
void maxmin_cp(const float* __restrict__ x, float* __restrict__ out)
{
    __shared__ uint2    meta[IN_F + 16];  // {w row elem-offset, dup-half2 x}
    __shared__ unsigned xdup[IN_F];       // natural order (dense fallback)
    __shared__ unsigned mrg[4][OUT_F / 2];// per-warp partial bests (4 KB)
    __shared__ int s_c1, s_c2;

    const int t    = threadIdx.x;
    const int b    = blockIdx.x;
    const int warp = t >> 5;
    const int lane = t & 31;
    const unsigned lmlt = (1u << lane) - 1u;

    if (t == 0) { s_c1 = 0; s_c2 = 0; }
    __syncthreads();

    // ---- classify + reserve compaction slots ----
    float4 xq = ((const float4*)x)[b * (IN_F / 4) + t];
    float xv[4] = {xq.x, xq.y, xq.z, xq.w};
    unsigned m1[4], m2[4];
    int      b1[4], b2[4];
    bool     p1[4], p2[4];
#pragma unroll
    for (int u = 0; u < 4; u++) {
        __half2 d = __float2half2_rn(xv[u]);
        xdup[t * 4 + u] = *(unsigned*)&d;
        p1[u] = (xv[u] >= TH1);
        p2[u] = (!p1[u]) && (xv[u] >= TH2);
        m1[u] = __ballot_sync(0xFFFFFFFFu, p1[u]);
        m2[u] = __ballot_sync(0xFFFFFFFFu, p2[u]);
        int base1 = 0, base2 = 0;
        if (lane == 0) {
            if (m1[u]) base1 = atomicAdd(&s_c1, __popc(m1[u]));
            if (m2[u]) base2 = atomicAdd(&s_c2, __popc(m2[u]));
        }
        b1[u] = __shfl_sync(0xFFFFFFFFu, base1, 0);
        b2[u] = __shfl_sync(0xFFFFFFFFu, base2, 0);
    }
    __syncthreads();
    const int C1 = s_c1;
    const int C2 = s_c2;

    // ---- scatter: G1 at [0,C1), G2 at [C1,C1+C2); zero-pad tail ----
#pragma unroll
    for (int u = 0; u < 4; u++) {
        int idx = t * 4 + u;
        unsigned xd = xdup[idx];
        if (p1[u])
            meta[b1[u] + __popc(m1[u] & lmlt)] =
                make_uint2((unsigned)(idx * (OUT_F / 2)), xd);
        else if (p2[u])
            meta[C1 + b2[u] + __popc(m2[u] & lmlt)] =
                make_uint2((unsigned)(idx * (OUT_F / 2)), xd);
    }
    if (t < 16) meta[C1 + C2 + t] = make_uint2(0u, 0u);  // x=0 pad: harmless
    __syncthreads();

    // ---- candidate-parallel scan: warp w takes rows 16*it + 4w + q ----
    // lane owns 16 outputs: uints co..co+7 of a packed W row (2x LDG.128).
    const int co = lane * 8;
    __half2 acc[8];
#pragma unroll
    for (int i = 0; i < 8; i++) acc[i] = __float2half2_rn(0.f);

    auto scan_rows = [&](int rbeg, int nit) {
#pragma unroll 1
        for (int it = 0; it < nit; it++) {
            const int rb = rbeg + it * 16 + warp * 4;
            uint4 v[8];
            unsigned xh[4];
#pragma unroll
            for (int q = 0; q < 4; q++) {          // 8 independent LDG.128
                uint2 m = meta[rb + q];
                xh[q] = m.y;
                const uint4* p = (const uint4*)&g_wh[m.x + co];
                v[2 * q]     = p[0];
                v[2 * q + 1] = p[1];
            }
#pragma unroll
            for (int q = 0; q < 4; q++) {
                __half2 xw = *(__half2*)&xh[q];
                acc[0] = __hmax2(acc[0], __hmin2(xw, *(__half2*)&v[2*q].x));
                acc[1] = __hmax2(acc[1], __hmin2(xw, *(__half2*)&v[2*q].y));
                acc[2] = __hmax2(acc[2], __hmin2(xw, *(__half2*)&v[2*q].z));
                acc[3] = __hmax2(acc[3], __hmin2(xw, *(__half2*)&v[2*q].w));
                acc[4] = __hmax2(acc[4], __hmin2(xw, *(__half2*)&v[2*q+1].x));
                acc[5] = __hmax2(acc[5], __hmin2(xw, *(__half2*)&v[2*q+1].y));
                acc[6] = __hmax2(acc[6], __hmin2(xw, *(__half2*)&v[2*q+1].z));
                acc[7] = __hmax2(acc[7], __hmin2(xw, *(__half2*)&v[2*q+1].w));
            }
        }
    };

    auto merge_read = [&](__half2& best0, __half2& best1) {
        *(uint4*)&mrg[warp][co] =
            make_uint4(*(unsigned*)&acc[0], *(unsigned*)&acc[1],
                       *(unsigned*)&acc[2], *(unsigned*)&acc[3]);
        *(uint4*)&mrg[warp][co + 4] =
            make_uint4(*(unsigned*)&acc[4], *(unsigned*)&acc[5],
                       *(unsigned*)&acc[6], *(unsigned*)&acc[7]);
        __syncthreads();
        uint2 r0 = *(const uint2*)&mrg[0][2 * t];
        uint2 r1 = *(const uint2*)&mrg[1][2 * t];
        uint2 r2 = *(const uint2*)&mrg[2][2 * t];
        uint2 r3 = *(const uint2*)&mrg[3][2 * t];
        best0 = __hmax2(__hmax2(*(__half2*)&r0.x, *(__half2*)&r1.x),
                        __hmax2(*(__half2*)&r2.x, *(__half2*)&r3.x));
        best1 = __hmax2(__hmax2(*(__half2*)&r0.y, *(__half2*)&r1.y),
                        __hmax2(*(__half2*)&r2.y, *(__half2*)&r3.y));
    };

    // ---- tier 1 ----
    const int nit1 = (C1 + 15) >> 4;
    scan_rows(0, nit1);
    __half2 best0, best1;
    merge_read(best0, best1);

    const __half2 T1h = __float2half2_rn(TH1);
    bool pass = __hbge2(best0, T1h) && __hbge2(best1, T1h);
    if (!__syncthreads_and(pass)) {
        // ---- tier 2: remaining rows of G1+G2 ----
        const int done = nit1 * 16;
        int rem = C1 + C2 - done;
        if (rem > 0) scan_rows(done, (rem + 15) >> 4);
        merge_read(best0, best1);
        const __half2 T2h = __float2half2_rn(TH2);
        pass = __hbge2(best0, T2h) && __hbge2(best1, T2h);
        if (!__syncthreads_and(pass)) {
            // ---- dense fallback (arbitrary inputs; ~never for uniform) ----
            const int te = t * 2;
#pragma unroll 8
            for (int j = 0; j < IN_F; j++) {
                uint2 wv = *(const uint2*)&g_wh[j * (OUT_F / 2) + te];
                unsigned xd = xdup[j];
                __half2 xh = *(__half2*)&xd;
                best0 = __hmax2(best0, __hmin2(xh, *(__half2*)&wv.x));
                best1 = __hmax2(best1, __hmin2(xh, *(__half2*)&wv.y));
            }
        }
    }

    // ---- store 4 outputs (float4, coalesced) ----
    float2 a = __half22float2(best0);
    float2 d = __half22float2(best1);
    *(float4*)(out + b * OUT_F + t * 4) = make_float4(a.x, a.y, d.x, d.y);
}

extern "C" void kernel_launch(void* const* d_in, const int* in_sizes, int n_in,
                              void* d_out, int out_size)
{
    const float* x = (const float*)d_in[0];   // [1024, 512]
    const float* w = (const float*)d_in[1];   // [512, 512]
    float* out = (float*)d_out;               // [1024, 512]

    prep_w<<<128, 256>>>(w);
    maxmin_cp<<<B_DIM, THREADS>>>(x, out);
}